// round 1
// baseline (speedup 1.0000x reference)
#include <cuda_runtime.h>

// DynamicPooling (capsule-routing style) for B=64, N=4096, D=256, fp32.
// x: [B,N,D], m: [B,N,1]. Outputs: w [B,N] then s [B,D] packed into d_out.
//
// Schedule (6 full sweeps of x = 1.5 GB HBM traffic):
//   b = 0
//   repeat 3x:
//     w      = softmax(m*b, axis=N)                (tiny, [B,N])
//     sigma  = sum_n w_n * m_n * x_n               (sweep 1: two-stage reduce)
//     s      = squash(sigma)                       (tiny, [B,D])
//     b     += m_n * dot(s, x_n)                   (sweep 2: per-row dot)
//   w = softmax(b, axis=N)  (NO m factor — matches reference)
//
// All reductions are deterministic (no float atomics): sigma goes through a
// per-chunk partial buffer, then a fixed-order combine inside squash.

namespace {
constexpr int Bb = 64;
constexpr int Nn = 4096;
constexpr int Dd = 256;
constexpr int NCHUNK = 32;           // N-chunks for sigma partial reduction
constexpr int ROWS = Nn / NCHUNK;    // 128 rows per chunk
}

// Scratch (static device globals — no allocation allowed in kernel_launch)
__device__ float g_part[NCHUNK * Bb * Dd];  // 2 MB partial sigmas
__device__ float g_s[Bb * Dd];
__device__ float g_b[Bb * Nn];
__device__ float g_w[Bb * Nn];

__global__ void zero_b_kernel() {
    int i = blockIdx.x * blockDim.x + threadIdx.x;
    if (i < Bb * Nn) g_b[i] = 0.0f;
}

// Softmax over N per batch. use_m: logits = m*b (loop) vs b (final).
// out == nullptr -> write to g_w (internal); else write to d_out region.
__global__ void softmax_kernel(const float* __restrict__ m, int use_m,
                               float* __restrict__ out) {
    int b = blockIdx.x, t = threadIdx.x;
    const float* bb = g_b + (size_t)b * Nn;
    const float* mm = m + (size_t)b * Nn;

    float vals[16];
    float lmax = -3.4e38f;
#pragma unroll
    for (int i = 0; i < 16; i++) {
        int n = t + i * 256;
        float v = bb[n];
        if (use_m) v *= mm[n];
        vals[i] = v;
        lmax = fmaxf(lmax, v);
    }
    __shared__ float red[256];
    red[t] = lmax;
    __syncthreads();
#pragma unroll
    for (int s = 128; s > 0; s >>= 1) {
        if (t < s) red[t] = fmaxf(red[t], red[t + s]);
        __syncthreads();
    }
    float gmax = red[0];
    __syncthreads();

    float lsum = 0.0f;
#pragma unroll
    for (int i = 0; i < 16; i++) {
        vals[i] = expf(vals[i] - gmax);
        lsum += vals[i];
    }
    red[t] = lsum;
    __syncthreads();
#pragma unroll
    for (int s = 128; s > 0; s >>= 1) {
        if (t < s) red[t] += red[t + s];
        __syncthreads();
    }
    float inv = 1.0f / red[0];

    float* dst = out ? out : (float*)g_w;
#pragma unroll
    for (int i = 0; i < 16; i++)
        dst[(size_t)b * Nn + t + i * 256] = vals[i] * inv;
}

// sigma partial: block = (chunk c, batch b). Each block streams 128 rows x 256
// floats (128 KB) with float4 loads and produces one [D] partial vector.
__global__ void sigma_partial_kernel(const float* __restrict__ x,
                                     const float* __restrict__ m) {
    int b = blockIdx.y;
    int c = blockIdx.x;
    int n0 = c * ROWS;
    int t = threadIdx.x;

    __shared__ float wm[ROWS];
    if (t < ROWS) {
        int gi = b * Nn + n0 + t;
        wm[t] = g_w[gi] * m[gi];
    }
    __syncthreads();

    int dg = (t & 63) << 2;  // d offset (0,4,...,252)
    int nl = t >> 6;         // row lane 0..3
    const float* xb = x + ((size_t)b * Nn + n0) * Dd;

    float4 acc = make_float4(0.f, 0.f, 0.f, 0.f);
#pragma unroll 8
    for (int n = nl; n < ROWS; n += 4) {
        float4 v = *reinterpret_cast<const float4*>(xb + (size_t)n * Dd + dg);
        float cwm = wm[n];
        acc.x = fmaf(cwm, v.x, acc.x);
        acc.y = fmaf(cwm, v.y, acc.y);
        acc.z = fmaf(cwm, v.z, acc.z);
        acc.w = fmaf(cwm, v.w, acc.w);
    }

    __shared__ float4 part[256];
    part[t] = acc;
    __syncthreads();
    if (nl == 0) {
        float4 a0 = part[t], a1 = part[t + 64], a2 = part[t + 128], a3 = part[t + 192];
        float* dst = g_part + ((size_t)c * Bb + b) * Dd + dg;
        dst[0] = a0.x + a1.x + a2.x + a3.x;
        dst[1] = a0.y + a1.y + a2.y + a3.y;
        dst[2] = a0.z + a1.z + a2.z + a3.z;
        dst[3] = a0.w + a1.w + a2.w + a3.w;
    }
}

// Combine chunk partials (fixed order -> deterministic), then squash.
// out_s != nullptr on the last iteration -> also write s into d_out.
__global__ void squash_kernel(float* __restrict__ out_s) {
    int b = blockIdx.x, t = threadIdx.x;
    float v = 0.0f;
#pragma unroll
    for (int c = 0; c < NCHUNK; c++)
        v += g_part[((size_t)c * Bb + b) * Dd + t];

    __shared__ float red[256];
    red[t] = v * v;
    __syncthreads();
#pragma unroll
    for (int s = 128; s > 0; s >>= 1) {
        if (t < s) red[t] += red[t + s];
        __syncthreads();
    }
    float n2 = red[0];
    float norm = sqrtf(n2);
    float scale = n2 / (1.0f + n2) / (norm + 1e-8f);
    float sv = scale * v;
    g_s[b * Dd + t] = sv;
    if (out_s) out_s[b * Dd + t] = sv;
}

// b[b,n] += m[b,n] * dot(s_b, x[b,n,:]).  One warp per row, 2x float4 per lane.
__global__ void bupdate_kernel(const float* __restrict__ x,
                               const float* __restrict__ m) {
    int b = blockIdx.y;
    int t = threadIdx.x;
    int warp = t >> 5, lane = t & 31;

    __shared__ float s_sh[Dd];
    if (t < Dd) s_sh[t] = g_s[b * Dd + t];
    __syncthreads();

    int n = blockIdx.x * 8 + warp;
    const float* xr = x + ((size_t)b * Nn + n) * Dd;
    int d0 = lane << 2;
    float4 v0 = *reinterpret_cast<const float4*>(xr + d0);
    float4 v1 = *reinterpret_cast<const float4*>(xr + 128 + d0);

    float dot = v0.x * s_sh[d0] + v0.y * s_sh[d0 + 1] +
                v0.z * s_sh[d0 + 2] + v0.w * s_sh[d0 + 3] +
                v1.x * s_sh[128 + d0] + v1.y * s_sh[129 + d0] +
                v1.z * s_sh[130 + d0] + v1.w * s_sh[131 + d0];
#pragma unroll
    for (int o = 16; o > 0; o >>= 1)
        dot += __shfl_xor_sync(0xffffffffu, dot, o);

    if (lane == 0) {
        int gi = b * Nn + n;
        g_b[gi] += m[gi] * dot;
    }
}

extern "C" void kernel_launch(void* const* d_in, const int* in_sizes, int n_in,
                              void* d_out, int out_size) {
    (void)in_sizes; (void)n_in; (void)out_size;
    const float* x = (const float*)d_in[0];
    const float* m = (const float*)d_in[1];
    float* out = (float*)d_out;
    float* out_w = out;               // [B, N]
    float* out_s = out + Bb * Nn;     // [B, D]

    zero_b_kernel<<<(Bb * Nn) / 256, 256>>>();

    for (int it = 0; it < 3; ++it) {
        softmax_kernel<<<Bb, 256>>>(m, /*use_m=*/1, nullptr);
        sigma_partial_kernel<<<dim3(NCHUNK, Bb), 256>>>(x, m);
        squash_kernel<<<Bb, 256>>>(it == 2 ? out_s : nullptr);
        bupdate_kernel<<<dim3(Nn / 8, Bb), 256>>>(x, m);
    }
    // Final w = softmax(b) — note: NO m factor here, per reference.
    softmax_kernel<<<Bb, 256>>>(m, /*use_m=*/0, out_w);
}

// round 2
// speedup vs baseline: 1.5239x; 1.5239x over previous
#include <cuda_runtime.h>

// DynamicPooling, fused online-softmax schedule. B=64, N=4096, D=256, fp32.
// x: [B,N,D], m: [B,N,1]. Output: w [B,N] then s [B,D].
//
// 4 sweeps of x (vs naive 6):
//   sweep A (MODE 0): sigma1 partials with uniform weights (b=0).
//   combine+squash -> s1
//   sweep B (MODE 1, b=0): b1 = m*(x.s1); sigma2 partials with exp(m*b1) weights
//                          (online max/mass per warp, combined per block).
//   combine+squash -> s2
//   sweep C (MODE 1):      b2 = b1 + m*(x.s2); sigma3 partials.
//   combine+squash -> s3 (written to output)
//   sweep D (MODE 2):      b3 = b2 + m*(x.s3). (no sigma needed)
//   final softmax(b3) -> w (no m factor, per reference).
//
// All reductions fixed-order -> deterministic across graph replays.

namespace {
constexpr int Bb = 64;
constexpr int Nn = 4096;
constexpr int Dd = 256;
constexpr int NCHUNK = 32;            // N-chunks per batch
constexpr int ROWS = Nn / NCHUNK;     // 128 rows per block
constexpr int WARPS = 8;
constexpr int RPW = ROWS / WARPS;     // 16 rows per warp
}

// Scratch (device globals; no allocation allowed)
__device__ float g_part[NCHUNK * Bb * Dd];  // unnormalized sigma partials
__device__ float g_M[NCHUNK * Bb];          // per-chunk local max
__device__ float g_Z[NCHUNK * Bb];          // per-chunk local mass
__device__ float g_s[Bb * Dd];
__device__ float g_b[Bb * Nn];

// MODE 0: first sigma (uniform weights, no b).  MODE 1: b-update + next sigma.
// MODE 2: b-update only.  ZEROB: treat incoming b as 0 (first b-update).
template <int MODE, bool ZEROB>
__global__ void __launch_bounds__(256) fused_sweep_kernel(
    const float* __restrict__ x, const float* __restrict__ m) {
    const int b = blockIdx.y, c = blockIdx.x;
    const int t = threadIdx.x, w = t >> 5, l = t & 31;
    const int n0 = c * ROWS;

    __shared__ float s_sh[Dd];
    __shared__ float m_sh[ROWS];
    __shared__ float b_sh[ROWS];
    __shared__ float sm_acc[WARPS * Dd];
    __shared__ float sm_M[WARPS], sm_Z[WARPS];

    if (MODE != 0 && t < Dd) s_sh[t] = g_s[b * Dd + t];
    if (t < ROWS) {
        int gi = b * Nn + n0 + t;
        m_sh[t] = m[gi];
        if (MODE != 0) b_sh[t] = ZEROB ? 0.0f : g_b[gi];
    }
    __syncthreads();

    const float* xb = x + ((size_t)b * Nn + n0) * Dd;
    const int r0 = w * RPW;
    const int d0 = l << 2;

    // prefetch first row
    const float* xr = xb + (size_t)r0 * Dd;
    float4 v0 = *reinterpret_cast<const float4*>(xr + d0);
    float4 v1 = *reinterpret_cast<const float4*>(xr + 128 + d0);

    float acc[8] = {0, 0, 0, 0, 0, 0, 0, 0};
    float M = (MODE == 0) ? 0.0f : -1e30f;
    float Z = 0.0f;

    for (int i = 0; i < RPW; i++) {
        const int n = r0 + i;
        float4 a0 = v0, a1 = v1;
        if (i + 1 < RPW) {  // prefetch next row
            const float* xn = xb + (size_t)(n + 1) * Dd;
            v0 = *reinterpret_cast<const float4*>(xn + d0);
            v1 = *reinterpret_cast<const float4*>(xn + 128 + d0);
        }
        const float mn = m_sh[n];

        if (MODE == 0) {
            acc[0] = fmaf(mn, a0.x, acc[0]);
            acc[1] = fmaf(mn, a0.y, acc[1]);
            acc[2] = fmaf(mn, a0.z, acc[2]);
            acc[3] = fmaf(mn, a0.w, acc[3]);
            acc[4] = fmaf(mn, a1.x, acc[4]);
            acc[5] = fmaf(mn, a1.y, acc[5]);
            acc[6] = fmaf(mn, a1.z, acc[6]);
            acc[7] = fmaf(mn, a1.w, acc[7]);
            Z += 1.0f;
        } else {
            // row dot with s (butterfly -> all lanes hold full dot)
            float dot = a0.x * s_sh[d0]       + a0.y * s_sh[d0 + 1] +
                        a0.z * s_sh[d0 + 2]   + a0.w * s_sh[d0 + 3] +
                        a1.x * s_sh[128 + d0] + a1.y * s_sh[129 + d0] +
                        a1.z * s_sh[130 + d0] + a1.w * s_sh[131 + d0];
#pragma unroll
            for (int o = 16; o > 0; o >>= 1)
                dot += __shfl_xor_sync(0xffffffffu, dot, o);

            const float bnew = fmaf(mn, dot, b_sh[n]);
            if (l == 0) g_b[b * Nn + n0 + n] = bnew;

            if (MODE == 1) {
                const float logit = mn * bnew;
                const float Mn = fmaxf(M, logit);
                const float scale = __expf(M - Mn);
                const float e = __expf(logit - Mn);
                Z = fmaf(Z, scale, e);
                const float wv = e * mn;
                acc[0] = fmaf(wv, a0.x, acc[0] * scale);
                acc[1] = fmaf(wv, a0.y, acc[1] * scale);
                acc[2] = fmaf(wv, a0.z, acc[2] * scale);
                acc[3] = fmaf(wv, a0.w, acc[3] * scale);
                acc[4] = fmaf(wv, a1.x, acc[4] * scale);
                acc[5] = fmaf(wv, a1.y, acc[5] * scale);
                acc[6] = fmaf(wv, a1.z, acc[6] * scale);
                acc[7] = fmaf(wv, a1.w, acc[7] * scale);
                M = Mn;
            }
        }
    }

    if (MODE != 2) {
        // stash per-warp state, then block-level rescaled combine (fixed order)
        *reinterpret_cast<float4*>(&sm_acc[w * Dd + d0]) =
            make_float4(acc[0], acc[1], acc[2], acc[3]);
        *reinterpret_cast<float4*>(&sm_acc[w * Dd + 128 + d0]) =
            make_float4(acc[4], acc[5], acc[6], acc[7]);
        if (l == 0) { sm_M[w] = M; sm_Z[w] = Z; }
        __syncthreads();

        float Mb = sm_M[0];
#pragma unroll
        for (int k = 1; k < WARPS; k++) Mb = fmaxf(Mb, sm_M[k]);
        float sig = 0.0f;
#pragma unroll
        for (int k = 0; k < WARPS; k++)
            sig = fmaf(__expf(sm_M[k] - Mb), sm_acc[k * Dd + t], sig);
        g_part[((size_t)c * Bb + b) * Dd + t] = sig;
        if (t == 0) {
            float Zb = 0.0f;
#pragma unroll
            for (int k = 0; k < WARPS; k++)
                Zb = fmaf(__expf(sm_M[k] - Mb), sm_Z[k], Zb);
            g_M[c * Bb + b] = Mb;
            g_Z[c * Bb + b] = Zb;
        }
    }
}

// Per batch: rescale+combine 32 chunk partials, normalize, squash -> s.
__global__ void __launch_bounds__(256) combine_squash_kernel(float* __restrict__ out_s) {
    const int b = blockIdx.x, t = threadIdx.x;
    __shared__ float sm_M[NCHUNK], sm_Z[NCHUNK];
    if (t < NCHUNK) {
        sm_M[t] = g_M[t * Bb + b];
        sm_Z[t] = g_Z[t * Bb + b];
    }
    __syncthreads();

    float Mg = sm_M[0];
#pragma unroll
    for (int c = 1; c < NCHUNK; c++) Mg = fmaxf(Mg, sm_M[c]);

    float v = 0.0f, Zg = 0.0f;
#pragma unroll
    for (int c = 0; c < NCHUNK; c++) {
        const float e = __expf(sm_M[c] - Mg);
        v = fmaf(e, g_part[((size_t)c * Bb + b) * Dd + t], v);
        Zg = fmaf(e, sm_Z[c], Zg);
    }
    const float sigma = v / Zg;

    __shared__ float red[256];
    red[t] = sigma * sigma;
    __syncthreads();
#pragma unroll
    for (int s = 128; s > 0; s >>= 1) {
        if (t < s) red[t] += red[t + s];
        __syncthreads();
    }
    const float n2 = red[0];
    const float norm = sqrtf(n2);
    const float scale = n2 / (1.0f + n2) / (norm + 1e-8f);
    const float sv = scale * sigma;
    g_s[b * Dd + t] = sv;
    if (out_s) out_s[b * Dd + t] = sv;
}

// Final w = softmax(b) over N (no m factor). Exact 2-pass in-register.
__global__ void __launch_bounds__(256) final_softmax_kernel(float* __restrict__ out_w) {
    const int b = blockIdx.x, t = threadIdx.x;
    const float* bb = g_b + (size_t)b * Nn;

    float vals[16];
    float lmax = -3.4e38f;
#pragma unroll
    for (int i = 0; i < 16; i++) {
        vals[i] = bb[t + i * 256];
        lmax = fmaxf(lmax, vals[i]);
    }
    __shared__ float red[256];
    red[t] = lmax;
    __syncthreads();
#pragma unroll
    for (int s = 128; s > 0; s >>= 1) {
        if (t < s) red[t] = fmaxf(red[t], red[t + s]);
        __syncthreads();
    }
    const float gmax = red[0];
    __syncthreads();

    float lsum = 0.0f;
#pragma unroll
    for (int i = 0; i < 16; i++) {
        vals[i] = __expf(vals[i] - gmax);
        lsum += vals[i];
    }
    red[t] = lsum;
    __syncthreads();
#pragma unroll
    for (int s = 128; s > 0; s >>= 1) {
        if (t < s) red[t] += red[t + s];
        __syncthreads();
    }
    const float inv = 1.0f / red[0];
#pragma unroll
    for (int i = 0; i < 16; i++)
        out_w[(size_t)b * Nn + t + i * 256] = vals[i] * inv;
}

extern "C" void kernel_launch(void* const* d_in, const int* in_sizes, int n_in,
                              void* d_out, int out_size) {
    (void)in_sizes; (void)n_in; (void)out_size;
    const float* x = (const float*)d_in[0];
    const float* m = (const float*)d_in[1];
    float* out = (float*)d_out;
    float* out_w = out;             // [B, N]
    float* out_s = out + Bb * Nn;   // [B, D]

    const dim3 grid(NCHUNK, Bb);

    fused_sweep_kernel<0, false><<<grid, 256>>>(x, m);   // sigma1 (uniform w)
    combine_squash_kernel<<<Bb, 256>>>(nullptr);         // -> s1
    fused_sweep_kernel<1, true><<<grid, 256>>>(x, m);    // b1 + sigma2 partials
    combine_squash_kernel<<<Bb, 256>>>(nullptr);         // -> s2
    fused_sweep_kernel<1, false><<<grid, 256>>>(x, m);   // b2 + sigma3 partials
    combine_squash_kernel<<<Bb, 256>>>(out_s);           // -> s3 (output)
    fused_sweep_kernel<2, false><<<grid, 256>>>(x, m);   // b3
    final_softmax_kernel<<<Bb, 256>>>(out_w);            // w = softmax(b3)
}

// round 3
// speedup vs baseline: 1.6236x; 1.0654x over previous
#include <cuda_runtime.h>

// DynamicPooling, fused online-softmax + L2-resident batch groups.
// B=64, N=4096, D=256, fp32. x: [B,N,D], m: [B,N,1].
// Output: w [B,N] then s [B,D].
//
// Batches are independent -> process in groups of 16 (64 MB of x, fits L2).
// Per group, 4 sweeps of the group's x slice:
//   sweep 0 (MODE 0): sigma1 partials, uniform weights (DRAM -> L2 fill)
//   sweep 1 (MODE 1, ZEROB): head-combine -> s1; b1 = m*(x.s1); sigma2 partials
//   sweep 2 (MODE 1):        head-combine -> s2; b2 += ...;    sigma3 partials
//   sweep 3 (MODE 2):        head-combine -> s3 (write out);   b3 += ...
// Sweeps 1-3 read x from L2. Head-combine = per-batch rescaled chunk combine
// + squash, recomputed redundantly per block (fixed order -> deterministic).
// Final: w = softmax(b3) over N (no m factor, per reference).

namespace {
constexpr int Bb = 64;
constexpr int Nn = 4096;
constexpr int Dd = 256;
constexpr int NCHUNK = 32;            // N-chunks per batch
constexpr int ROWS = Nn / NCHUNK;     // 128 rows per block
constexpr int WARPS = 8;
constexpr int RPW = ROWS / WARPS;     // 16 rows per warp
constexpr int GRP = 16;               // batches per L2-resident group
}

// Scratch (device globals; no allocation allowed)
__device__ float g_part[Bb * NCHUNK * Dd];  // unnormalized sigma partials [b][c][d]
__device__ float g_M[Bb * NCHUNK];          // per-chunk local max   [b][c]
__device__ float g_Z[Bb * NCHUNK];          // per-chunk local mass  [b][c]
__device__ float g_b[Bb * Nn];

// MODE 0: sigma only (uniform weights, b ignored).
// MODE 1: head-combine -> s; b-update; next-sigma partials.
// MODE 2: head-combine -> s (optionally written to out_s); b-update only.
// ZEROB : incoming b treated as 0 (first b-update).
template <int MODE, bool ZEROB>
__global__ void __launch_bounds__(256) fused_sweep_kernel(
    const float* __restrict__ x, const float* __restrict__ m,
    int b0, float* __restrict__ out_s) {
    const int b = b0 + blockIdx.y;          // global batch
    const int c = blockIdx.x;               // chunk
    const int t = threadIdx.x, w = t >> 5, l = t & 31;
    const int n0 = c * ROWS;

    __shared__ float s_sh[Dd];
    __shared__ float m_sh[ROWS];
    __shared__ float b_sh[ROWS];
    __shared__ float sm_acc[WARPS * Dd];
    __shared__ float sm_M[WARPS], sm_Z[WARPS];
    __shared__ float red[256];
    __shared__ float hm[NCHUNK], hz[NCHUNK];

    if (t < ROWS) {
        int gi = b * Nn + n0 + t;
        m_sh[t] = m[gi];
        if (MODE != 0) b_sh[t] = ZEROB ? 0.0f : g_b[gi];
    }

    if (MODE != 0) {
        // ---- head-combine: rebuild s for this batch from previous sweep's
        // partials (redundant per block; fixed order -> deterministic). ----
        if (t < NCHUNK) {
            hm[t] = g_M[b * NCHUNK + t];
            hz[t] = g_Z[b * NCHUNK + t];
        }
        __syncthreads();
        float Mg = hm[0];
#pragma unroll
        for (int k = 1; k < NCHUNK; k++) Mg = fmaxf(Mg, hm[k]);
        float v = 0.0f, Zg = 0.0f;
#pragma unroll
        for (int k = 0; k < NCHUNK; k++) {
            const float e = __expf(hm[k] - Mg);
            v = fmaf(e, g_part[((size_t)b * NCHUNK + k) * Dd + t], v);
            Zg = fmaf(e, hz[k], Zg);
        }
        const float sigma = v / Zg;
        red[t] = sigma * sigma;
        __syncthreads();
#pragma unroll
        for (int s = 128; s > 0; s >>= 1) {
            if (t < s) red[t] += red[t + s];
            __syncthreads();
        }
        const float n2 = red[0];
        const float norm = sqrtf(n2);
        const float sv = (n2 / (1.0f + n2) / (norm + 1e-8f)) * sigma;
        s_sh[t] = sv;
        if (MODE == 2 && c == 0 && out_s) out_s[b * Dd + t] = sv;
    }
    __syncthreads();

    const float* xb = x + ((size_t)b * Nn + n0) * Dd;
    const int r0 = w * RPW;
    const int d0 = l << 2;

    // prefetch first row
    const float* xr = xb + (size_t)r0 * Dd;
    float4 v0 = *reinterpret_cast<const float4*>(xr + d0);
    float4 v1 = *reinterpret_cast<const float4*>(xr + 128 + d0);

    float acc[8] = {0, 0, 0, 0, 0, 0, 0, 0};
    float M = (MODE == 0) ? 0.0f : -1e30f;
    float Z = 0.0f;

    for (int i = 0; i < RPW; i++) {
        const int n = r0 + i;
        float4 a0 = v0, a1 = v1;
        if (i + 1 < RPW) {  // prefetch next row
            const float* xn = xb + (size_t)(n + 1) * Dd;
            v0 = *reinterpret_cast<const float4*>(xn + d0);
            v1 = *reinterpret_cast<const float4*>(xn + 128 + d0);
        }
        const float mn = m_sh[n];

        if (MODE == 0) {
            acc[0] = fmaf(mn, a0.x, acc[0]);
            acc[1] = fmaf(mn, a0.y, acc[1]);
            acc[2] = fmaf(mn, a0.z, acc[2]);
            acc[3] = fmaf(mn, a0.w, acc[3]);
            acc[4] = fmaf(mn, a1.x, acc[4]);
            acc[5] = fmaf(mn, a1.y, acc[5]);
            acc[6] = fmaf(mn, a1.z, acc[6]);
            acc[7] = fmaf(mn, a1.w, acc[7]);
            Z += 1.0f;
        } else {
            // row dot with s (butterfly -> all lanes hold full dot)
            float dot = a0.x * s_sh[d0]       + a0.y * s_sh[d0 + 1] +
                        a0.z * s_sh[d0 + 2]   + a0.w * s_sh[d0 + 3] +
                        a1.x * s_sh[128 + d0] + a1.y * s_sh[129 + d0] +
                        a1.z * s_sh[130 + d0] + a1.w * s_sh[131 + d0];
#pragma unroll
            for (int o = 16; o > 0; o >>= 1)
                dot += __shfl_xor_sync(0xffffffffu, dot, o);

            const float bnew = fmaf(mn, dot, b_sh[n]);
            if (l == 0) g_b[b * Nn + n0 + n] = bnew;

            if (MODE == 1) {
                const float logit = mn * bnew;
                const float Mn = fmaxf(M, logit);
                const float scale = __expf(M - Mn);
                const float e = __expf(logit - Mn);
                Z = fmaf(Z, scale, e);
                const float wv = e * mn;
                acc[0] = fmaf(wv, a0.x, acc[0] * scale);
                acc[1] = fmaf(wv, a0.y, acc[1] * scale);
                acc[2] = fmaf(wv, a0.z, acc[2] * scale);
                acc[3] = fmaf(wv, a0.w, acc[3] * scale);
                acc[4] = fmaf(wv, a1.x, acc[4] * scale);
                acc[5] = fmaf(wv, a1.y, acc[5] * scale);
                acc[6] = fmaf(wv, a1.z, acc[6] * scale);
                acc[7] = fmaf(wv, a1.w, acc[7] * scale);
                M = Mn;
            }
        }
    }

    if (MODE != 2) {
        // per-warp state -> block-level rescaled combine (fixed order)
        *reinterpret_cast<float4*>(&sm_acc[w * Dd + d0]) =
            make_float4(acc[0], acc[1], acc[2], acc[3]);
        *reinterpret_cast<float4*>(&sm_acc[w * Dd + 128 + d0]) =
            make_float4(acc[4], acc[5], acc[6], acc[7]);
        if (l == 0) { sm_M[w] = M; sm_Z[w] = Z; }
        __syncthreads();

        float Mb = sm_M[0];
#pragma unroll
        for (int k = 1; k < WARPS; k++) Mb = fmaxf(Mb, sm_M[k]);
        float sig = 0.0f;
#pragma unroll
        for (int k = 0; k < WARPS; k++)
            sig = fmaf(__expf(sm_M[k] - Mb), sm_acc[k * Dd + t], sig);
        g_part[((size_t)b * NCHUNK + c) * Dd + t] = sig;
        if (t == 0) {
            float Zb = 0.0f;
#pragma unroll
            for (int k = 0; k < WARPS; k++)
                Zb = fmaf(__expf(sm_M[k] - Mb), sm_Z[k], Zb);
            g_M[b * NCHUNK + c] = Mb;
            g_Z[b * NCHUNK + c] = Zb;
        }
    }
}

// Final w = softmax(b) over N (no m factor). Exact 2-pass in-register.
__global__ void __launch_bounds__(256) final_softmax_kernel(float* __restrict__ out_w) {
    const int b = blockIdx.x, t = threadIdx.x;
    const float* bb = g_b + (size_t)b * Nn;

    float vals[16];
    float lmax = -3.4e38f;
#pragma unroll
    for (int i = 0; i < 16; i++) {
        vals[i] = bb[t + i * 256];
        lmax = fmaxf(lmax, vals[i]);
    }
    __shared__ float red[256];
    red[t] = lmax;
    __syncthreads();
#pragma unroll
    for (int s = 128; s > 0; s >>= 1) {
        if (t < s) red[t] = fmaxf(red[t], red[t + s]);
        __syncthreads();
    }
    const float gmax = red[0];
    __syncthreads();

    float lsum = 0.0f;
#pragma unroll
    for (int i = 0; i < 16; i++) {
        vals[i] = __expf(vals[i] - gmax);
        lsum += vals[i];
    }
    red[t] = lsum;
    __syncthreads();
#pragma unroll
    for (int s = 128; s > 0; s >>= 1) {
        if (t < s) red[t] += red[t + s];
        __syncthreads();
    }
    const float inv = 1.0f / red[0];
#pragma unroll
    for (int i = 0; i < 16; i++)
        out_w[(size_t)b * Nn + t + i * 256] = vals[i] * inv;
}

extern "C" void kernel_launch(void* const* d_in, const int* in_sizes, int n_in,
                              void* d_out, int out_size) {
    (void)in_sizes; (void)n_in; (void)out_size;
    const float* x = (const float*)d_in[0];
    const float* m = (const float*)d_in[1];
    float* out = (float*)d_out;
    float* out_w = out;             // [B, N]
    float* out_s = out + Bb * Nn;   // [B, D]

    const dim3 grid(NCHUNK, GRP);

    for (int g = 0; g < Bb / GRP; ++g) {
        const int b0 = g * GRP;
        // sweep 0: sigma1 (uniform weights); fills L2 with this group's x
        fused_sweep_kernel<0, false><<<grid, 256>>>(x, m, b0, nullptr);
        // sweep 1: s1; b1; sigma2 partials (x from L2)
        fused_sweep_kernel<1, true><<<grid, 256>>>(x, m, b0, nullptr);
        // sweep 2: s2; b2; sigma3 partials (x from L2)
        fused_sweep_kernel<1, false><<<grid, 256>>>(x, m, b0, nullptr);
        // sweep 3: s3 (written to out_s); b3 (x from L2)
        fused_sweep_kernel<2, false><<<grid, 256>>>(x, m, b0, out_s);
    }
    final_softmax_kernel<<<Bb, 256>>>(out_w);  // w = softmax(b3)
}